// round 14
// baseline (speedup 1.0000x reference)
#include <cuda_runtime.h>
#include <math.h>
#include <stdint.h>

#define N_NODES 20000
#define N_EDGES 320000
#define T_STEPS 16
#define HG 64
#define HT 128
#define G3 384
#define NT (N_NODES * T_STEPS)
#define LN_EPS 1e-5f

// ===================== scratch (static device globals) =======================
__device__ int   g_cnt[N_NODES];
__device__ int   g_fill[N_NODES];
__device__ int   g_rowptr[N_NODES + 1];
__device__ int   g_col[N_EDGES];
__device__ float g_h0_all[NT * HG];
__device__ float g_ins_all[NT * (2 * HG)];
__device__ float g_H_all[NT * HG];

// pre-split packed-bf16 weights, hi/lo interleaved (uint2), fragment-contiguous:
// P[(rowblk*K2 + c)*8 + (row&7)] = {hi, lo}
__device__ uint2 g_ws1p[8  * 64 * 8];   // ws1: 64 rows, K2=64
__device__ uint2 g_wgp[48 * 96 * 8];    // [Wih|Whh]: 384 rows, K=192, K2=96

__device__ __forceinline__ float warp_sum(float v) {
#pragma unroll
    for (int o = 16; o; o >>= 1) v += __shfl_xor_sync(0xFFFFFFFFu, v, o);
    return v;
}

__device__ __forceinline__ float fast_sigmoid(float x) {
    return __fdividef(1.f, 1.f + __expf(-x));
}
__device__ __forceinline__ float fast_tanh(float x) {
    return 1.f - __fdividef(2.f, __expf(2.f * x) + 1.f);
}

// bf16x2 split: returns packed hi pair, writes packed lo pair (lo = v - hi)
__device__ __forceinline__ uint32_t pack_split(float x0, float x1, uint32_t& lo) {
    uint32_t hi;
    asm("cvt.rn.bf16x2.f32 %0, %1, %2;" : "=r"(hi) : "f"(x1), "f"(x0));
    float h0 = __uint_as_float(hi << 16);
    float h1 = __uint_as_float(hi & 0xFFFF0000u);
    float l0 = x0 - h0, l1 = x1 - h1;
    asm("cvt.rn.bf16x2.f32 %0, %1, %2;" : "=r"(lo) : "f"(l1), "f"(l0));
    return hi;
}

// m16n8k16 bf16 MMA (sm_80+ generic PTX)
__device__ __forceinline__ void mma16(float* d, const uint32_t* a, uint32_t b0, uint32_t b1) {
    asm volatile(
        "mma.sync.aligned.m16n8k16.row.col.f32.bf16.bf16.f32 "
        "{%0,%1,%2,%3}, {%4,%5,%6,%7}, {%8,%9}, {%0,%1,%2,%3};"
        : "+f"(d[0]), "+f"(d[1]), "+f"(d[2]), "+f"(d[3])
        : "r"(a[0]), "r"(a[1]), "r"(a[2]), "r"(a[3]), "r"(b0), "r"(b1));
}

// bf16x3 against interleaved fragments
__device__ __forceinline__ void mma_x3(float* d, const uint32_t* ah, const uint32_t* al,
                                       uint2 w0, uint2 w1) {
    mma16(d, al, w0.x, w1.x);   // lo_A * hi_B (small terms first)
    mma16(d, ah, w0.y, w1.y);   // hi_A * lo_B
    mma16(d, ah, w0.x, w1.x);   // hi_A * hi_B
}

// ------------------------- CSR build -----------------------------------------
__global__ void k_hist(const int* __restrict__ ei) {
    int e = blockIdx.x * blockDim.x + threadIdx.x;
    if (e < N_EDGES) atomicAdd(&g_cnt[ei[N_EDGES + e]], 1);
}

__global__ void k_scan() {
    __shared__ int sh[1024];
    __shared__ int base;
    int tid = threadIdx.x;
    if (tid == 0) { base = 0; g_rowptr[0] = 0; }
    __syncthreads();
    for (int start = 0; start < N_NODES; start += 1024) {
        int i = start + tid;
        int v = (i < N_NODES) ? g_cnt[i] : 0;
        sh[tid] = v;
        __syncthreads();
        for (int off = 1; off < 1024; off <<= 1) {
            int t = (tid >= off) ? sh[tid - off] : 0;
            __syncthreads();
            sh[tid] += t;
            __syncthreads();
        }
        if (i < N_NODES) g_rowptr[i + 1] = base + sh[tid];
        __syncthreads();
        if (tid == 1023) base += sh[1023];
        __syncthreads();
    }
    for (int i = tid; i < N_NODES; i += 1024) { g_cnt[i] = 0; g_fill[i] = 0; }
}

__global__ void k_scatter(const int* __restrict__ ei) {
    int e = blockIdx.x * blockDim.x + threadIdx.x;
    if (e >= N_EDGES) return;
    int d = ei[N_EDGES + e];
    int p = atomicAdd(&g_fill[d], 1);
    g_col[g_rowptr[d] + p] = ei[e];
}

// ------------------- weight pre-split kernels ---------------------------------
// Destinations referenced in DEVICE code only (GB300/ATS host-shadow trap).
__global__ void k_prep_ws1(const float* __restrict__ Wl1, const float* __restrict__ Wr1) {
    int idx = blockIdx.x * blockDim.x + threadIdx.x;   // 64 * 64
    if (idx >= 64 * 64) return;
    int m = idx >> 6, c = idx & 63;
    int k0 = 2 * c;
    float v0 = (k0 < 64) ? Wl1[k0 * 64 + m] : Wr1[(k0 - 64) * 64 + m];
    float v1 = (k0 + 1 < 64) ? Wl1[(k0 + 1) * 64 + m] : Wr1[(k0 - 63) * 64 + m];
    uint32_t lo, hi = pack_split(v0, v1, lo);
    g_ws1p[((m >> 3) * 64 + c) * 8 + (m & 7)] = make_uint2(hi, lo);
}

// combined [Wih (K 0..63) | Whh (K 64..191)], 384 rows, K2=96
__global__ void k_prep_wg(const float* __restrict__ Wih, const float* __restrict__ Whh) {
    int idx = blockIdx.x * blockDim.x + threadIdx.x;   // 384 * 96
    if (idx >= G3 * 96) return;
    int row = idx / 96, c = idx % 96;
    int k0 = 2 * c, k1 = 2 * c + 1;                    // pairs never straddle k=64
    float v0 = (k0 < 64) ? Wih[row * 64 + k0] : Whh[row * 128 + k0 - 64];
    float v1 = (k1 < 64) ? Wih[row * 64 + k1] : Whh[row * 128 + k1 - 64];
    uint32_t lo, hi = pack_split(v0, v1, lo);
    g_wgp[((row >> 3) * 96 + c) * 8 + (row & 7)] = make_uint2(hi, lo);
}

// ------------------- layer 0 (batched): agg + SAGE + LN + relu ----------------
__global__ void k_stack0_all(const float* __restrict__ x_seq,
                             const float* __restrict__ Wl, const float* __restrict__ Wr,
                             const float* __restrict__ b0,
                             const float* __restrict__ g, const float* __restrict__ beta) {
    int t = blockIdx.y;
    int n = blockIdx.x * 8 + (threadIdx.x >> 5);
    int lane = threadIdx.x & 31;
    if (n >= N_NODES) return;
    const float* xt = x_seq + t * N_NODES;
    int beg = g_rowptr[n], end = g_rowptr[n + 1];
    float acc = 0.f;
    for (int i = beg + lane; i < end; i += 32) acc += xt[g_col[i]];
    acc = warp_sum(acc);
    float deg = fmaxf((float)(end - beg), 1.f);
    float agg = acc / deg;
    float xv = xt[n];
    float v0 = agg * Wl[lane]      + xv * Wr[lane]      + b0[lane];
    float v1 = agg * Wl[lane + 32] + xv * Wr[lane + 32] + b0[lane + 32];
    float mu = warp_sum(v0 + v1) * (1.f / 64.f);
    float d0 = v0 - mu, d1 = v1 - mu;
    float var = warp_sum(d0 * d0 + d1 * d1) * (1.f / 64.f);
    float inv = rsqrtf(var + LN_EPS);
    float h0a = fmaxf(d0 * inv * g[lane]      + beta[lane], 0.f);
    float h0b = fmaxf(d1 * inv * g[lane + 32] + beta[lane + 32], 0.f);
    size_t row = (size_t)t * N_NODES + n;
    g_h0_all[row * HG + lane]      = h0a;
    g_h0_all[row * HG + lane + 32] = h0b;
    g_ins_all[row * 128 + 64 + lane]      = h0a;
    g_ins_all[row * 128 + 64 + lane + 32] = h0b;
}

// ------------------- layer 1 aggregate (batched, 2-way unrolled) --------------
__global__ void k_agg1_all() {
    int t = blockIdx.y;
    int n = blockIdx.x * 8 + (threadIdx.x >> 5);
    int lane = threadIdx.x & 31;
    if (n >= N_NODES) return;
    const float* h0t = g_h0_all + (size_t)t * N_NODES * HG;
    int beg = g_rowptr[n], end = g_rowptr[n + 1];
    float a0 = 0.f, a1 = 0.f, c0 = 0.f, c1 = 0.f;
    int i = beg;
    for (; i + 1 < end; i += 2) {
        int s0 = g_col[i], s1 = g_col[i + 1];
        a0 += h0t[s0 * HG + lane];
        a1 += h0t[s0 * HG + lane + 32];
        c0 += h0t[s1 * HG + lane];
        c1 += h0t[s1 * HG + lane + 32];
    }
    if (i < end) {
        int s = g_col[i];
        a0 += h0t[s * HG + lane];
        a1 += h0t[s * HG + lane + 32];
    }
    a0 += c0; a1 += c1;
    float inv = 1.f / fmaxf((float)(end - beg), 1.f);
    size_t row = (size_t)t * N_NODES + n;
    g_ins_all[row * 128 + lane]      = a0 * inv;
    g_ins_all[row * 128 + lane + 32] = a1 * inv;
}

// ===================== sage1 bf16x3 GEMM =======================================
// S = ins_all(NTx128) @ ws1^T(64x128) + b1; LN + relu -> g_H_all
__global__ void __launch_bounds__(256)
k_sage(const float* __restrict__ bias, const float* __restrict__ p0,
       const float* __restrict__ p1) {
    constexpr int K2  = 64;
    constexpr int LDK = 68;
    constexpr int BM  = 128;

    extern __shared__ uint32_t smu[];
    uint32_t* Ah = smu;
    uint32_t* Al = smu + BM * LDK;
    float*    S  = (float*)smu;                 // aliases Ah after MMAs

    int tid = threadIdx.x;
    size_t rowBase = (size_t)blockIdx.x * BM;

    for (int idx = tid; idx < BM * 32; idx += 256) {
        int r = idx >> 5, c4 = idx & 31;
        float4 v = *(const float4*)(g_ins_all + (rowBase + r) * 128 + c4 * 4);
        uint32_t lo0, lo1;
        uint32_t hi0 = pack_split(v.x, v.y, lo0);
        uint32_t hi1 = pack_split(v.z, v.w, lo1);
        int j = r * LDK + c4 * 2;
        Ah[j] = hi0; Ah[j + 1] = hi1;
        Al[j] = lo0; Al[j + 1] = lo1;
    }
    __syncthreads();

    int warp = tid >> 5, lane = tid & 31;
    int wm = warp >> 1, wn = warp & 1;          // 4 x 2 warps, WM=32, WN=32
    int g = lane >> 2, tg = lane & 3;
    int m0 = wm * 32, n0 = wn * 32;

    float acc[2][4][4] = {};
#pragma unroll
    for (int kk = 0; kk < K2; kk += 8) {
        uint32_t ah[2][4], al[2][4];
#pragma unroll
        for (int mf = 0; mf < 2; mf++) {
            int base = (m0 + 16 * mf + g) * LDK + kk + tg;
            ah[mf][0] = Ah[base];               al[mf][0] = Al[base];
            ah[mf][1] = Ah[base + 8 * LDK];     al[mf][1] = Al[base + 8 * LDK];
            ah[mf][2] = Ah[base + 4];           al[mf][2] = Al[base + 4];
            ah[mf][3] = Ah[base + 8 * LDK + 4]; al[mf][3] = Al[base + 8 * LDK + 4];
        }
#pragma unroll
        for (int nf = 0; nf < 4; nf++) {
            int fo = (((n0 + 8 * nf) >> 3) * K2 + kk + tg) * 8 + g;
            uint2 w0 = g_ws1p[fo], w1 = g_ws1p[fo + 32];
#pragma unroll
            for (int mf = 0; mf < 2; mf++)
                mma_x3(acc[mf][nf], ah[mf], al[mf], w0, w1);
        }
    }

    __syncthreads();
#pragma unroll
    for (int mf = 0; mf < 2; mf++)
#pragma unroll
        for (int nf = 0; nf < 4; nf++) {
            int r = m0 + 16 * mf + g;
            int c = n0 + 8 * nf + 2 * tg;
            S[r * 68 + c]           = acc[mf][nf][0] + bias[c];
            S[r * 68 + c + 1]       = acc[mf][nf][1] + bias[c + 1];
            S[(r + 8) * 68 + c]     = acc[mf][nf][2] + bias[c];
            S[(r + 8) * 68 + c + 1] = acc[mf][nf][3] + bias[c + 1];
        }
    __syncthreads();
#pragma unroll
    for (int i = 0; i < 16; i++) {
        int r = warp * 16 + i;
        float v0 = S[r * 68 + lane];
        float v1 = S[r * 68 + lane + 32];
        float mu = warp_sum(v0 + v1) * (1.f / 64.f);
        float d0 = v0 - mu, d1 = v1 - mu;
        float var = warp_sum(d0 * d0 + d1 * d1) * (1.f / 64.f);
        float inv = rsqrtf(var + LN_EPS);
        size_t rowg = rowBase + r;
        g_H_all[rowg * HG + lane]      = fmaxf(d0 * inv * p0[lane]      + p1[lane], 0.f);
        g_H_all[rowg * HG + lane + 32] = fmaxf(d1 * inv * p0[lane + 32] + p1[lane + 32], 0.f);
    }
}

// ===================== persistent GRU chain (gi fused, 3-pass gates) ===========
// One launch. CTA owns 32 nodes; loops t=0..15 with h resident in smem.
// Per step: A = [H_t | h] staged+split in smem; three accumulation passes
// (r -> n -> z) keep peak live accumulators at 32 so occ 3 fits the reg cap.
__global__ void __launch_bounds__(256, 3)
k_chain(const float* __restrict__ bih, const float* __restrict__ bhh,
        const float* __restrict__ headW, const float* __restrict__ headb,
        float* __restrict__ y) {
    constexpr int K2  = 96;
    constexpr int LDK = 100;                    // %32==4 -> conflict-free
    constexpr int BM  = 32;                     // 20000 = 625 * 32 exactly

    __shared__ float    hs[BM][HT + 4];
    __shared__ uint32_t Ah[BM * LDK];
    __shared__ uint32_t Al[BM * LDK];

    int tid = threadIdx.x, warp = tid >> 5, lane = tid & 31;
    int nodeBase = blockIdx.x * BM;
    int g = lane >> 2, tg = lane & 3;
    int n0 = warp * 16;                         // 8 warps x WN=16 over 128 cols

    for (int i = tid; i < BM * HT; i += 256) hs[i >> 7][i & 127] = 0.f;
    __syncthreads();

    for (int t = 0; t < T_STEPS; t++) {
        const float* Ht = g_H_all + ((size_t)t * N_NODES + nodeBase) * HG;
        if (t + 1 < T_STEPS && tid < 64) {
            const char* gp = (const char*)(g_H_all + ((size_t)(t + 1) * N_NODES + nodeBase) * HG);
            asm volatile("prefetch.global.L2 [%0];" :: "l"(gp + (size_t)tid * 128));
        }
        // ---- stage A: [H_t | h] -> packed bf16 hi/lo ----
        for (int i = tid; i < BM * 48; i += 256) {
            int r = i / 48, q = i % 48;
            float4 v = (q < 16) ? *(const float4*)(Ht + (size_t)r * HG + q * 4)
                                : *(const float4*)(&hs[r][(q - 16) * 4]);
            uint32_t lo0, lo1;
            uint32_t hi0 = pack_split(v.x, v.y, lo0);
            uint32_t hi1 = pack_split(v.z, v.w, lo1);
            int j = r * LDK + q * 2;
            Ah[j] = hi0; Ah[j + 1] = hi1;
            Al[j] = lo0; Al[j + 1] = lo1;
        }
        __syncthreads();

        // helper macro: load A fragments for one kk
#define LOAD_A(kk)                                                          \
        uint32_t ah[2][4], al[2][4];                                        \
        _Pragma("unroll")                                                   \
        for (int mf = 0; mf < 2; mf++) {                                    \
            int base = (16 * mf + g) * LDK + (kk) + tg;                     \
            ah[mf][0] = Ah[base];               al[mf][0] = Al[base];       \
            ah[mf][1] = Ah[base + 8 * LDK];     al[mf][1] = Al[base + 8 * LDK]; \
            ah[mf][2] = Ah[base + 4];           al[mf][2] = Al[base + 4];   \
            ah[mf][3] = Ah[base + 8 * LDK + 4]; al[mf][3] = Al[base + 8 * LDK + 4]; \
        }

        // ---- pass 1: r gate (rows 0..127 of combined W) ----
        float rv[2][2][4];
        {
            float acc[2][2][4] = {};
#pragma unroll
            for (int kk = 0; kk < K2; kk += 8) {
                LOAD_A(kk)
#pragma unroll
                for (int nf = 0; nf < 2; nf++) {
                    int nrow = n0 + 8 * nf;
                    int fo = ((nrow >> 3) * K2 + kk + tg) * 8 + g;
                    uint2 w0 = g_wgp[fo], w1 = g_wgp[fo + 32];
#pragma unroll
                    for (int mf = 0; mf < 2; mf++)
                        mma_x3(acc[mf][nf], ah[mf], al[mf], w0, w1);
                }
            }
#pragma unroll
            for (int mf = 0; mf < 2; mf++)
#pragma unroll
                for (int nf = 0; nf < 2; nf++)
#pragma unroll
                    for (int q = 0; q < 4; q++) {
                        int c = n0 + 8 * nf + 2 * tg + (q & 1);
                        rv[mf][nf][q] = fast_sigmoid(acc[mf][nf][q] + bih[c] + bhh[c]);
                    }
        }

        // ---- pass 2: n gate (rows 256..383), k-split ni/nh; consume rv ----
        float nv[2][2][4];
        {
            float acc[2][2][2][4] = {};         // [ni/nh][mf][nf][4]
#pragma unroll
            for (int kk = 0; kk < K2; kk += 8) {
                LOAD_A(kk)
                int at = (kk < 32) ? 0 : 1;
#pragma unroll
                for (int nf = 0; nf < 2; nf++) {
                    int nrow = 2 * HT + n0 + 8 * nf;
                    int fo = ((nrow >> 3) * K2 + kk + tg) * 8 + g;
                    uint2 w0 = g_wgp[fo], w1 = g_wgp[fo + 32];
#pragma unroll
                    for (int mf = 0; mf < 2; mf++)
                        mma_x3(acc[at][mf][nf], ah[mf], al[mf], w0, w1);
                }
            }
#pragma unroll
            for (int mf = 0; mf < 2; mf++)
#pragma unroll
                for (int nf = 0; nf < 2; nf++)
#pragma unroll
                    for (int q = 0; q < 4; q++) {
                        int c = n0 + 8 * nf + 2 * tg + (q & 1);
                        nv[mf][nf][q] = fast_tanh(acc[0][mf][nf][q] + bih[256 + c] +
                                        rv[mf][nf][q] * (acc[1][mf][nf][q] + bhh[256 + c]));
                    }
        }

        // ---- pass 3: z gate (rows 128..255); combine immediately ----
        {
            float acc[2][2][4] = {};
#pragma unroll
            for (int kk = 0; kk < K2; kk += 8) {
                LOAD_A(kk)
#pragma unroll
                for (int nf = 0; nf < 2; nf++) {
                    int nrow = HT + n0 + 8 * nf;
                    int fo = ((nrow >> 3) * K2 + kk + tg) * 8 + g;
                    uint2 w0 = g_wgp[fo], w1 = g_wgp[fo + 32];
#pragma unroll
                    for (int mf = 0; mf < 2; mf++)
                        mma_x3(acc[mf][nf], ah[mf], al[mf], w0, w1);
                }
            }
#pragma unroll
            for (int mf = 0; mf < 2; mf++)
#pragma unroll
                for (int nf = 0; nf < 2; nf++)
#pragma unroll
                    for (int q = 0; q < 4; q++) {
                        int c = n0 + 8 * nf + 2 * tg + (q & 1);
                        int nl = 16 * mf + g + 8 * (q >> 1);
                        float z = fast_sigmoid(acc[mf][nf][q] + bih[128 + c] + bhh[128 + c]);
                        hs[nl][c] = (1.f - z) * nv[mf][nf][q] + z * hs[nl][c];
                    }
        }
#undef LOAD_A
        __syncthreads();
    }

    // ---- fused head: y[node] = dot(h, headW) + headb ----
#pragma unroll
    for (int i = 0; i < 4; i++) {
        int r = warp * 4 + i;
        float acc = 0.f;
#pragma unroll
        for (int q = 0; q < 4; q++) {
            int j = lane + 32 * q;
            acc += hs[r][j] * headW[j];
        }
        acc = warp_sum(acc);
        if (lane == 0) y[nodeBase + r] = acc + headb[0];
    }
}

// ------------------------- launch ------------------------------------------------
extern "C" void kernel_launch(void* const* d_in, const int* in_sizes, int n_in,
                              void* d_out, int out_size) {
    const float* x_seq = (const float*)d_in[0];
    const int*   ei    = (const int*)d_in[1];
    const float* W_l0  = (const float*)d_in[2];
    const float* W_r0  = (const float*)d_in[3];
    const float* b0    = (const float*)d_in[4];
    const float* ln0g  = (const float*)d_in[5];
    const float* ln0b  = (const float*)d_in[6];
    const float* W_l1  = (const float*)d_in[7];
    const float* W_r1  = (const float*)d_in[8];
    const float* b1    = (const float*)d_in[9];
    const float* ln1g  = (const float*)d_in[10];
    const float* ln1b  = (const float*)d_in[11];
    const float* Wih   = (const float*)d_in[12];
    const float* Whh   = (const float*)d_in[13];
    const float* bih   = (const float*)d_in[14];
    const float* bhh   = (const float*)d_in[15];
    const float* headW = (const float*)d_in[16];
    const float* headb = (const float*)d_in[17];
    float* y = (float*)d_out;

    const int SMEM_S = 128 * 68 * 2 * 4;   // 69632
    cudaFuncSetAttribute(k_sage, cudaFuncAttributeMaxDynamicSharedMemorySize, SMEM_S);

    // CSR build (k_scan re-zeroes cnt/fill for graph replays)
    k_hist<<<(N_EDGES + 255) / 256, 256>>>(ei);
    k_scan<<<1, 1024>>>();
    k_scatter<<<(N_EDGES + 255) / 256, 256>>>(ei);

    // phase A (all timesteps in parallel)
    dim3 gridA((N_NODES + 7) / 8, T_STEPS);
    k_stack0_all<<<gridA, 256>>>(x_seq, W_l0, W_r0, b0, ln0g, ln0b);
    k_prep_ws1<<<(64 * 64 + 255) / 256, 256>>>(W_l1, W_r1);
    k_prep_wg<<<(G3 * 96 + 255) / 256, 256>>>(Wih, Whh);
    k_agg1_all<<<gridA, 256>>>();

    k_sage<<<NT / 128, 256, SMEM_S>>>(b1, ln1g, ln1b);

    // phase B: single persistent-chain launch (gi GEMM + GRU + head fused)
    k_chain<<<N_NODES / 32, 256>>>(bih, bhh, headW, headb, y);
}

// round 15
// speedup vs baseline: 2.4604x; 2.4604x over previous
#include <cuda_runtime.h>
#include <math.h>
#include <stdint.h>

#define N_NODES 20000
#define N_EDGES 320000
#define T_STEPS 16
#define HG 64
#define HT 128
#define G3 384
#define NT (N_NODES * T_STEPS)
#define LN_EPS 1e-5f

// ===================== scratch (static device globals) =======================
__device__ int   g_cnt[N_NODES];
__device__ int   g_fill[N_NODES];
__device__ int   g_rowptr[N_NODES + 1];
__device__ int   g_col[N_EDGES];
__device__ float g_h0_all[NT * HG];
__device__ float g_ins_all[NT * (2 * HG)];
__device__ float g_H_all[NT * HG];

// pre-split packed-bf16 weights, hi/lo interleaved (uint2), fragment-contiguous:
// P[(rowblk*K2 + c)*8 + (row&7)] = {hi, lo}
__device__ uint2 g_ws1p[8  * 64 * 8];   // ws1: 64 rows, K2=64
__device__ uint2 g_wgp[48 * 96 * 8];    // [Wih|Whh]: 384 rows, K=192, K2=96

__device__ __forceinline__ float warp_sum(float v) {
#pragma unroll
    for (int o = 16; o; o >>= 1) v += __shfl_xor_sync(0xFFFFFFFFu, v, o);
    return v;
}

__device__ __forceinline__ float fast_sigmoid(float x) {
    return __fdividef(1.f, 1.f + __expf(-x));
}
__device__ __forceinline__ float fast_tanh(float x) {
    return 1.f - __fdividef(2.f, __expf(2.f * x) + 1.f);
}

// bf16x2 split: returns packed hi pair, writes packed lo pair (lo = v - hi)
__device__ __forceinline__ uint32_t pack_split(float x0, float x1, uint32_t& lo) {
    uint32_t hi;
    asm("cvt.rn.bf16x2.f32 %0, %1, %2;" : "=r"(hi) : "f"(x1), "f"(x0));
    float h0 = __uint_as_float(hi << 16);
    float h1 = __uint_as_float(hi & 0xFFFF0000u);
    float l0 = x0 - h0, l1 = x1 - h1;
    asm("cvt.rn.bf16x2.f32 %0, %1, %2;" : "=r"(lo) : "f"(l1), "f"(l0));
    return hi;
}

// m16n8k16 bf16 MMA (sm_80+ generic PTX)
__device__ __forceinline__ void mma16(float* d, const uint32_t* a, uint32_t b0, uint32_t b1) {
    asm volatile(
        "mma.sync.aligned.m16n8k16.row.col.f32.bf16.bf16.f32 "
        "{%0,%1,%2,%3}, {%4,%5,%6,%7}, {%8,%9}, {%0,%1,%2,%3};"
        : "+f"(d[0]), "+f"(d[1]), "+f"(d[2]), "+f"(d[3])
        : "r"(a[0]), "r"(a[1]), "r"(a[2]), "r"(a[3]), "r"(b0), "r"(b1));
}

// bf16x3 against interleaved fragments
__device__ __forceinline__ void mma_x3(float* d, const uint32_t* ah, const uint32_t* al,
                                       uint2 w0, uint2 w1) {
    mma16(d, al, w0.x, w1.x);   // lo_A * hi_B (small terms first)
    mma16(d, ah, w0.y, w1.y);   // hi_A * lo_B
    mma16(d, ah, w0.x, w1.x);   // hi_A * hi_B
}

// ------------------------- CSR build -----------------------------------------
__global__ void k_hist(const int* __restrict__ ei) {
    int e = blockIdx.x * blockDim.x + threadIdx.x;
    if (e < N_EDGES) atomicAdd(&g_cnt[ei[N_EDGES + e]], 1);
}

__global__ void k_scan() {
    __shared__ int sh[1024];
    __shared__ int base;
    int tid = threadIdx.x;
    if (tid == 0) { base = 0; g_rowptr[0] = 0; }
    __syncthreads();
    for (int start = 0; start < N_NODES; start += 1024) {
        int i = start + tid;
        int v = (i < N_NODES) ? g_cnt[i] : 0;
        sh[tid] = v;
        __syncthreads();
        for (int off = 1; off < 1024; off <<= 1) {
            int t = (tid >= off) ? sh[tid - off] : 0;
            __syncthreads();
            sh[tid] += t;
            __syncthreads();
        }
        if (i < N_NODES) g_rowptr[i + 1] = base + sh[tid];
        __syncthreads();
        if (tid == 1023) base += sh[1023];
        __syncthreads();
    }
    for (int i = tid; i < N_NODES; i += 1024) { g_cnt[i] = 0; g_fill[i] = 0; }
}

__global__ void k_scatter(const int* __restrict__ ei) {
    int e = blockIdx.x * blockDim.x + threadIdx.x;
    if (e >= N_EDGES) return;
    int d = ei[N_EDGES + e];
    int p = atomicAdd(&g_fill[d], 1);
    g_col[g_rowptr[d] + p] = ei[e];
}

// ------------------- weight pre-split kernels ---------------------------------
// Destinations referenced in DEVICE code only (GB300/ATS host-shadow trap).
__global__ void k_prep_ws1(const float* __restrict__ Wl1, const float* __restrict__ Wr1) {
    int idx = blockIdx.x * blockDim.x + threadIdx.x;   // 64 * 64
    if (idx >= 64 * 64) return;
    int m = idx >> 6, c = idx & 63;
    int k0 = 2 * c;
    float v0 = (k0 < 64) ? Wl1[k0 * 64 + m] : Wr1[(k0 - 64) * 64 + m];
    float v1 = (k0 + 1 < 64) ? Wl1[(k0 + 1) * 64 + m] : Wr1[(k0 - 63) * 64 + m];
    uint32_t lo, hi = pack_split(v0, v1, lo);
    g_ws1p[((m >> 3) * 64 + c) * 8 + (m & 7)] = make_uint2(hi, lo);
}

// combined [Wih (K 0..63) | Whh (K 64..191)], 384 rows, K2=96
__global__ void k_prep_wg(const float* __restrict__ Wih, const float* __restrict__ Whh) {
    int idx = blockIdx.x * blockDim.x + threadIdx.x;   // 384 * 96
    if (idx >= G3 * 96) return;
    int row = idx / 96, c = idx % 96;
    int k0 = 2 * c, k1 = 2 * c + 1;                    // pairs never straddle k=64
    float v0 = (k0 < 64) ? Wih[row * 64 + k0] : Whh[row * 128 + k0 - 64];
    float v1 = (k1 < 64) ? Wih[row * 64 + k1] : Whh[row * 128 + k1 - 64];
    uint32_t lo, hi = pack_split(v0, v1, lo);
    g_wgp[((row >> 3) * 96 + c) * 8 + (row & 7)] = make_uint2(hi, lo);
}

// ------------------- layer 0 (batched): agg + SAGE + LN + relu ----------------
__global__ void k_stack0_all(const float* __restrict__ x_seq,
                             const float* __restrict__ Wl, const float* __restrict__ Wr,
                             const float* __restrict__ b0,
                             const float* __restrict__ g, const float* __restrict__ beta) {
    int t = blockIdx.y;
    int n = blockIdx.x * 8 + (threadIdx.x >> 5);
    int lane = threadIdx.x & 31;
    if (n >= N_NODES) return;
    const float* xt = x_seq + t * N_NODES;
    int beg = g_rowptr[n], end = g_rowptr[n + 1];
    float acc = 0.f;
    for (int i = beg + lane; i < end; i += 32) acc += xt[g_col[i]];
    acc = warp_sum(acc);
    float deg = fmaxf((float)(end - beg), 1.f);
    float agg = acc / deg;
    float xv = xt[n];
    float v0 = agg * Wl[lane]      + xv * Wr[lane]      + b0[lane];
    float v1 = agg * Wl[lane + 32] + xv * Wr[lane + 32] + b0[lane + 32];
    float mu = warp_sum(v0 + v1) * (1.f / 64.f);
    float d0 = v0 - mu, d1 = v1 - mu;
    float var = warp_sum(d0 * d0 + d1 * d1) * (1.f / 64.f);
    float inv = rsqrtf(var + LN_EPS);
    float h0a = fmaxf(d0 * inv * g[lane]      + beta[lane], 0.f);
    float h0b = fmaxf(d1 * inv * g[lane + 32] + beta[lane + 32], 0.f);
    size_t row = (size_t)t * N_NODES + n;
    g_h0_all[row * HG + lane]      = h0a;
    g_h0_all[row * HG + lane + 32] = h0b;
    g_ins_all[row * 128 + 64 + lane]      = h0a;
    g_ins_all[row * 128 + 64 + lane + 32] = h0b;
}

// ------------------- layer 1 aggregate (batched, 2-way unrolled) --------------
__global__ void k_agg1_all() {
    int t = blockIdx.y;
    int n = blockIdx.x * 8 + (threadIdx.x >> 5);
    int lane = threadIdx.x & 31;
    if (n >= N_NODES) return;
    const float* h0t = g_h0_all + (size_t)t * N_NODES * HG;
    int beg = g_rowptr[n], end = g_rowptr[n + 1];
    float a0 = 0.f, a1 = 0.f, c0 = 0.f, c1 = 0.f;
    int i = beg;
    for (; i + 1 < end; i += 2) {
        int s0 = g_col[i], s1 = g_col[i + 1];
        a0 += h0t[s0 * HG + lane];
        a1 += h0t[s0 * HG + lane + 32];
        c0 += h0t[s1 * HG + lane];
        c1 += h0t[s1 * HG + lane + 32];
    }
    if (i < end) {
        int s = g_col[i];
        a0 += h0t[s * HG + lane];
        a1 += h0t[s * HG + lane + 32];
    }
    a0 += c0; a1 += c1;
    float inv = 1.f / fmaxf((float)(end - beg), 1.f);
    size_t row = (size_t)t * N_NODES + n;
    g_ins_all[row * 128 + lane]      = a0 * inv;
    g_ins_all[row * 128 + lane + 32] = a1 * inv;
}

// ===================== sage1 bf16x3 GEMM =======================================
// S = ins_all(NTx128) @ ws1^T(64x128) + b1; LN + relu -> g_H_all
__global__ void __launch_bounds__(256)
k_sage(const float* __restrict__ bias, const float* __restrict__ p0,
       const float* __restrict__ p1) {
    constexpr int K2  = 64;
    constexpr int LDK = 68;
    constexpr int BM  = 128;

    extern __shared__ uint32_t smu[];
    uint32_t* Ah = smu;
    uint32_t* Al = smu + BM * LDK;
    float*    S  = (float*)smu;                 // aliases Ah after MMAs

    int tid = threadIdx.x;
    size_t rowBase = (size_t)blockIdx.x * BM;

    for (int idx = tid; idx < BM * 32; idx += 256) {
        int r = idx >> 5, c4 = idx & 31;
        float4 v = *(const float4*)(g_ins_all + (rowBase + r) * 128 + c4 * 4);
        uint32_t lo0, lo1;
        uint32_t hi0 = pack_split(v.x, v.y, lo0);
        uint32_t hi1 = pack_split(v.z, v.w, lo1);
        int j = r * LDK + c4 * 2;
        Ah[j] = hi0; Ah[j + 1] = hi1;
        Al[j] = lo0; Al[j + 1] = lo1;
    }
    __syncthreads();

    int warp = tid >> 5, lane = tid & 31;
    int wm = warp >> 1, wn = warp & 1;          // 4 x 2 warps, WM=32, WN=32
    int g = lane >> 2, tg = lane & 3;
    int m0 = wm * 32, n0 = wn * 32;

    float acc[2][4][4] = {};
#pragma unroll
    for (int kk = 0; kk < K2; kk += 8) {
        uint32_t ah[2][4], al[2][4];
#pragma unroll
        for (int mf = 0; mf < 2; mf++) {
            int base = (m0 + 16 * mf + g) * LDK + kk + tg;
            ah[mf][0] = Ah[base];               al[mf][0] = Al[base];
            ah[mf][1] = Ah[base + 8 * LDK];     al[mf][1] = Al[base + 8 * LDK];
            ah[mf][2] = Ah[base + 4];           al[mf][2] = Al[base + 4];
            ah[mf][3] = Ah[base + 8 * LDK + 4]; al[mf][3] = Al[base + 8 * LDK + 4];
        }
#pragma unroll
        for (int nf = 0; nf < 4; nf++) {
            int fo = (((n0 + 8 * nf) >> 3) * K2 + kk + tg) * 8 + g;
            uint2 w0 = g_ws1p[fo], w1 = g_ws1p[fo + 32];
#pragma unroll
            for (int mf = 0; mf < 2; mf++)
                mma_x3(acc[mf][nf], ah[mf], al[mf], w0, w1);
        }
    }

    __syncthreads();
#pragma unroll
    for (int mf = 0; mf < 2; mf++)
#pragma unroll
        for (int nf = 0; nf < 4; nf++) {
            int r = m0 + 16 * mf + g;
            int c = n0 + 8 * nf + 2 * tg;
            S[r * 68 + c]           = acc[mf][nf][0] + bias[c];
            S[r * 68 + c + 1]       = acc[mf][nf][1] + bias[c + 1];
            S[(r + 8) * 68 + c]     = acc[mf][nf][2] + bias[c];
            S[(r + 8) * 68 + c + 1] = acc[mf][nf][3] + bias[c + 1];
        }
    __syncthreads();
#pragma unroll
    for (int i = 0; i < 16; i++) {
        int r = warp * 16 + i;
        float v0 = S[r * 68 + lane];
        float v1 = S[r * 68 + lane + 32];
        float mu = warp_sum(v0 + v1) * (1.f / 64.f);
        float d0 = v0 - mu, d1 = v1 - mu;
        float var = warp_sum(d0 * d0 + d1 * d1) * (1.f / 64.f);
        float inv = rsqrtf(var + LN_EPS);
        size_t rowg = rowBase + r;
        g_H_all[rowg * HG + lane]      = fmaxf(d0 * inv * p0[lane]      + p1[lane], 0.f);
        g_H_all[rowg * HG + lane + 32] = fmaxf(d1 * inv * p0[lane + 32] + p1[lane + 32], 0.f);
    }
}

// ===================== persistent GRU chain (gi fused, single pass) ============
// One launch, 313 CTAs x 512 threads. CTA owns 64 nodes; loops t=0..15 with h
// resident in smem. 16 warps: each owns an 8-col N-slice (NF=1) across all 64
// rows (MF=4) — doubles weight-fragment reuse vs BM=32 (halves L2 weight
// traffic, the measured chain bottleneck). Same bf16x3 arithmetic as R13.
__global__ void __launch_bounds__(512, 1)
k_chain(const float* __restrict__ bih, const float* __restrict__ bhh,
        const float* __restrict__ headW, const float* __restrict__ headb,
        float* __restrict__ y) {
    constexpr int K2  = 96;
    constexpr int LDK = 100;                    // %32==4 -> conflict-free
    constexpr int BM  = 64;
    constexpr int LHS = HT + 4;                 // hs row stride (floats)

    extern __shared__ uint32_t smu[];
    float*    hs = (float*)smu;                 // [64][132]
    uint32_t* Ah = smu + BM * LHS;              // [64*100]
    uint32_t* Al = Ah + BM * LDK;

    int tid = threadIdx.x, warp = tid >> 5, lane = tid & 31;
    int nodeBase = blockIdx.x * BM;
    int g = lane >> 2, tg = lane & 3;
    int n0 = warp * 8;                          // 16 warps x 8 cols = 128

    for (int i = tid; i < BM * HT; i += 512) hs[(i >> 7) * LHS + (i & 127)] = 0.f;
    __syncthreads();

    for (int t = 0; t < T_STEPS; t++) {
        const float* Ht = g_H_all + ((size_t)t * N_NODES + nodeBase) * HG;
        if (t + 1 < T_STEPS && tid < 128) {
            const char* gp = (const char*)(g_H_all + ((size_t)(t + 1) * N_NODES + nodeBase) * HG);
            asm volatile("prefetch.global.L2 [%0];" :: "l"(gp + (size_t)tid * 128));
        }
        // ---- stage A: [H_t (q<16) | h (q>=16)] -> packed bf16 hi/lo ----
        for (int i = tid; i < BM * 48; i += 512) {
            int r = i / 48, q = i % 48;
            float4 v = make_float4(0.f, 0.f, 0.f, 0.f);
            if (q < 16) {
                if (nodeBase + r < N_NODES)
                    v = *(const float4*)(Ht + (size_t)r * HG + q * 4);
            } else {
                v = *(const float4*)(hs + r * LHS + (q - 16) * 4);
            }
            uint32_t lo0, lo1;
            uint32_t hi0 = pack_split(v.x, v.y, lo0);
            uint32_t hi1 = pack_split(v.z, v.w, lo1);
            int j = r * LDK + q * 2;
            Ah[j] = hi0; Ah[j + 1] = hi1;
            Al[j] = lo0; Al[j + 1] = lo1;
        }
        __syncthreads();

        float acc[4][4][4] = {};                // [r,z,n_i,n_h][MF=4][4]
#pragma unroll
        for (int kk = 0; kk < K2; kk += 8) {
            uint32_t ah[4][4], al[4][4];
#pragma unroll
            for (int mf = 0; mf < 4; mf++) {
                int base = (16 * mf + g) * LDK + kk + tg;
                ah[mf][0] = Ah[base];               al[mf][0] = Al[base];
                ah[mf][1] = Ah[base + 8 * LDK];     al[mf][1] = Al[base + 8 * LDK];
                ah[mf][2] = Ah[base + 4];           al[mf][2] = Al[base + 4];
                ah[mf][3] = Ah[base + 8 * LDK + 4]; al[mf][3] = Al[base + 8 * LDK + 4];
            }
#pragma unroll
            for (int gt = 0; gt < 3; gt++) {
                int at = (gt < 2) ? gt : ((kk < 32) ? 2 : 3);
                int nrow = gt * HT + n0;
                int fo = ((nrow >> 3) * K2 + kk + tg) * 8 + g;
                uint2 w0 = g_wgp[fo], w1 = g_wgp[fo + 32];
#pragma unroll
                for (int mf = 0; mf < 4; mf++)
                    mma_x3(acc[at][mf], ah[mf], al[mf], w0, w1);
            }
        }

        // ---- gates epilogue: fully in-register ----
#pragma unroll
        for (int mf = 0; mf < 4; mf++)
#pragma unroll
            for (int q = 0; q < 4; q++) {
                int c = n0 + 2 * tg + (q & 1);
                int nl = 16 * mf + g + 8 * (q >> 1);
                float r = fast_sigmoid(acc[0][mf][q] + bih[c] + bhh[c]);
                float z = fast_sigmoid(acc[1][mf][q] + bih[128 + c] + bhh[128 + c]);
                float n = fast_tanh(acc[2][mf][q] + bih[256 + c] +
                                    r * (acc[3][mf][q] + bhh[256 + c]));
                hs[nl * LHS + c] = (1.f - z) * n + z * hs[nl * LHS + c];
            }
        __syncthreads();
    }

    // ---- fused head: y[node] = dot(h, headW) + headb ----
#pragma unroll
    for (int i = 0; i < 4; i++) {
        int r = warp * 4 + i;                   // 16 warps x 4 = 64 rows
        float acc = 0.f;
#pragma unroll
        for (int q = 0; q < 4; q++) {
            int j = lane + 32 * q;
            acc += hs[r * LHS + j] * headW[j];
        }
        acc = warp_sum(acc);
        if (lane == 0 && nodeBase + r < N_NODES) y[nodeBase + r] = acc + headb[0];
    }
}

// ------------------------- launch ------------------------------------------------
extern "C" void kernel_launch(void* const* d_in, const int* in_sizes, int n_in,
                              void* d_out, int out_size) {
    const float* x_seq = (const float*)d_in[0];
    const int*   ei    = (const int*)d_in[1];
    const float* W_l0  = (const float*)d_in[2];
    const float* W_r0  = (const float*)d_in[3];
    const float* b0    = (const float*)d_in[4];
    const float* ln0g  = (const float*)d_in[5];
    const float* ln0b  = (const float*)d_in[6];
    const float* W_l1  = (const float*)d_in[7];
    const float* W_r1  = (const float*)d_in[8];
    const float* b1    = (const float*)d_in[9];
    const float* ln1g  = (const float*)d_in[10];
    const float* ln1b  = (const float*)d_in[11];
    const float* Wih   = (const float*)d_in[12];
    const float* Whh   = (const float*)d_in[13];
    const float* bih   = (const float*)d_in[14];
    const float* bhh   = (const float*)d_in[15];
    const float* headW = (const float*)d_in[16];
    const float* headb = (const float*)d_in[17];
    float* y = (float*)d_out;

    const int SMEM_S = 128 * 68 * 2 * 4;                    // 69632
    const int SMEM_C = (64 * 132 + 64 * 100 * 2) * 4;       // 84992
    cudaFuncSetAttribute(k_sage,  cudaFuncAttributeMaxDynamicSharedMemorySize, SMEM_S);
    cudaFuncSetAttribute(k_chain, cudaFuncAttributeMaxDynamicSharedMemorySize, SMEM_C);

    // CSR build (k_scan re-zeroes cnt/fill for graph replays)
    k_hist<<<(N_EDGES + 255) / 256, 256>>>(ei);
    k_scan<<<1, 1024>>>();
    k_scatter<<<(N_EDGES + 255) / 256, 256>>>(ei);

    // phase A (all timesteps in parallel)
    dim3 gridA((N_NODES + 7) / 8, T_STEPS);
    k_stack0_all<<<gridA, 256>>>(x_seq, W_l0, W_r0, b0, ln0g, ln0b);
    k_prep_ws1<<<(64 * 64 + 255) / 256, 256>>>(W_l1, W_r1);
    k_prep_wg<<<(G3 * 96 + 255) / 256, 256>>>(Wih, Whh);
    k_agg1_all<<<gridA, 256>>>();

    k_sage<<<NT / 128, 256, SMEM_S>>>(b1, ln1g, ln1b);

    // phase B: single persistent-chain launch (gi GEMM + GRU + head fused)
    k_chain<<<(N_NODES + 63) / 64, 512, SMEM_C>>>(bih, bhh, headW, headb, y);
}